// round 1
// baseline (speedup 1.0000x reference)
#include <cuda_runtime.h>
#include <math.h>

#define BATCH 4
#define SEQ   8192
#define DMODEL 1024
#define NH    16
#define DK    64
#define QKVN  (3*DMODEL)

// Scratch buffers (allocation-free rule: __device__ globals)
__device__ float g_qkv[(size_t)BATCH*SEQ*QKVN];   // [B,S,3*DM], q/k pre-activated
__device__ float g_attn[(size_t)BATCH*SEQ*DMODEL];// [B,S,DM]
__device__ float g_kv[BATCH*NH*DK*DK];            // [B,H,DK,DK]
__device__ float g_ksum[BATCH*NH*DK];             // [B,H,DK]

// ---------------------------------------------------------------------------
// Zero kv/ksum accumulators (must run every launch: atomics accumulate)
// ---------------------------------------------------------------------------
__global__ void zero_kv_kernel() {
    int i = blockIdx.x * 256 + threadIdx.x;
    if (i < BATCH*NH*DK*DK) g_kv[i] = 0.0f;
    if (i < BATCH*NH*DK)    g_ksum[i] = 0.0f;
}

// ---------------------------------------------------------------------------
// SGEMM: C[M,N] = A[M,K] @ B[K,N], all row-major. BM=BN=128, BK=8,
// 256 threads, 8x8 per-thread microtile, double-buffered smem.
// ACT: apply elu(x)+1 == (x>0 ? x+1 : exp(x)) to columns < 2048 (q,k slices).
// ---------------------------------------------------------------------------
template<bool ACT>
__global__ void __launch_bounds__(256) sgemm_kernel(
    const float* __restrict__ A, const float* __restrict__ B,
    float* __restrict__ C, int M, int N, int K)
{
    __shared__ float As[2][8][128];
    __shared__ float Bs[2][8][128];

    const int tid  = threadIdx.x;
    const int col0 = blockIdx.x * 128;
    const int row0 = blockIdx.y * 128;

    // A tile loads: 128 rows x 8 cols; one float4 per thread
    const int ar = tid >> 1;          // 0..127
    const int ac = (tid & 1) * 4;     // 0 or 4
    // B tile loads: 8 rows x 128 cols; one float4 per thread
    const int br = tid >> 5;          // 0..7
    const int bc = (tid & 31) * 4;    // 0..124

    const float* Aptr = A + (size_t)(row0 + ar) * K + ac;
    const float* Bptr = B + (size_t)br * N + col0 + bc;

    const int trow = (tid >> 4) * 8;  // 0..120
    const int tcol = (tid & 15) * 8;  // 0..120

    float acc[8][8];
    #pragma unroll
    for (int i = 0; i < 8; ++i)
        #pragma unroll
        for (int j = 0; j < 8; ++j) acc[i][j] = 0.0f;

    // prologue: fill buffer 0
    {
        float4 av = *(const float4*)(Aptr);
        float4 bv = *(const float4*)(Bptr);
        As[0][ac+0][ar] = av.x; As[0][ac+1][ar] = av.y;
        As[0][ac+2][ar] = av.z; As[0][ac+3][ar] = av.w;
        *(float4*)&Bs[0][br][bc] = bv;
    }
    __syncthreads();

    const int nk = K / 8;
    int cur = 0;
    for (int kt = 0; kt < nk; ++kt) {
        float4 av, bv;
        const bool has_next = (kt + 1 < nk);
        if (has_next) {
            av = *(const float4*)(Aptr + (size_t)(kt+1)*8);
            bv = *(const float4*)(Bptr + (size_t)(kt+1)*8*N);
        }
        #pragma unroll
        for (int k = 0; k < 8; ++k) {
            float a[8], b[8];
            *(float4*)&a[0] = *(float4*)&As[cur][k][trow];
            *(float4*)&a[4] = *(float4*)&As[cur][k][trow+4];
            *(float4*)&b[0] = *(float4*)&Bs[cur][k][tcol];
            *(float4*)&b[4] = *(float4*)&Bs[cur][k][tcol+4];
            #pragma unroll
            for (int i = 0; i < 8; ++i)
                #pragma unroll
                for (int j = 0; j < 8; ++j)
                    acc[i][j] += a[i] * b[j];
        }
        if (has_next) {
            const int nxt = cur ^ 1;
            As[nxt][ac+0][ar] = av.x; As[nxt][ac+1][ar] = av.y;
            As[nxt][ac+2][ar] = av.z; As[nxt][ac+3][ar] = av.w;
            *(float4*)&Bs[nxt][br][bc] = bv;
            __syncthreads();
            cur = nxt;
        }
    }

    // Epilogue. Activation applies uniformly per block: col tile is 128-wide
    // and the q/k|v boundary (2048) is 128-aligned.
    const bool doact = ACT && (col0 < 2048);
    #pragma unroll
    for (int i = 0; i < 8; ++i) {
        float v[8];
        #pragma unroll
        for (int j = 0; j < 8; ++j) v[j] = acc[i][j];
        if (doact) {
            #pragma unroll
            for (int j = 0; j < 8; ++j)
                v[j] = (v[j] > 0.0f) ? (v[j] + 1.0f) : expf(v[j]);
        }
        float* cp = C + (size_t)(row0 + trow + i) * N + col0 + tcol;
        *(float4*)(cp)     = *(float4*)&v[0];
        *(float4*)(cp + 4) = *(float4*)&v[4];
    }
}

// ---------------------------------------------------------------------------
// kv[b,h,d,f] = sum_n k[b,n,h,d] * v[b,n,h,f];  ksum[b,h,d] = sum_n k
// grid: (B*H, 16 chunks of 512 rows). 256 threads = 64 d-lanes x 4 f-groups.
// ---------------------------------------------------------------------------
__global__ void __launch_bounds__(256) kv_kernel() {
    const int bh = blockIdx.x;
    const int b  = bh >> 4, h = bh & 15;
    const int n0 = blockIdx.y * 512;

    __shared__ float ks[8][64];
    __shared__ float vs[8][64];

    const int tid = threadIdx.x;
    const int d   = tid & 63;
    const int fg  = tid >> 6;           // 0..3 -> f = fg*16 .. +16
    // load mapping: 8 rows x (16 k-float4 + 16 v-float4) = 256 float4
    const int rr   = tid >> 5;          // 0..7
    const int half = (tid >> 4) & 1;    // 0 = k, 1 = v
    const int c4   = tid & 15;

    float4 acc[4];
    #pragma unroll
    for (int i = 0; i < 4; ++i) acc[i] = make_float4(0.f,0.f,0.f,0.f);
    float ksacc = 0.0f;

    for (int r0 = 0; r0 < 512; r0 += 8) {
        const size_t rowbase = (size_t)(b*SEQ + n0 + r0 + rr) * QKVN;
        const float4 val = *(const float4*)(g_qkv + rowbase
                            + (half ? 2048 : 1024) + h*64 + c4*4);
        __syncthreads();   // previous iteration's reads complete
        if (half == 0) *(float4*)&ks[rr][c4*4] = val;
        else           *(float4*)&vs[rr][c4*4] = val;
        __syncthreads();
        #pragma unroll
        for (int r = 0; r < 8; ++r) {
            const float kd = ks[r][d];
            ksacc += kd;
            #pragma unroll
            for (int i4 = 0; i4 < 4; ++i4) {
                const float4 vv = *(const float4*)&vs[r][fg*16 + i4*4];
                acc[i4].x += kd * vv.x; acc[i4].y += kd * vv.y;
                acc[i4].z += kd * vv.z; acc[i4].w += kd * vv.w;
            }
        }
    }

    float* dst = g_kv + ((size_t)bh * DK + d) * DK + fg*16;
    #pragma unroll
    for (int i4 = 0; i4 < 4; ++i4) {
        atomicAdd(dst + i4*4 + 0, acc[i4].x);
        atomicAdd(dst + i4*4 + 1, acc[i4].y);
        atomicAdd(dst + i4*4 + 2, acc[i4].z);
        atomicAdd(dst + i4*4 + 3, acc[i4].w);
    }
    if (fg == 0) atomicAdd(&g_ksum[bh*DK + d], ksacc);
}

// ---------------------------------------------------------------------------
// attn[b,n,h*64+f] = (sum_d q[b,n,h,d]*kv[b,h,d,f]) / (q . ksum + 1e-6)
// grid: (S/64 tiles, B*H). Block: 256 = 16 row-groups x 16 f4-groups.
// ---------------------------------------------------------------------------
__global__ void __launch_bounds__(256) attn_kernel() {
    const int bh = blockIdx.y;
    const int b  = bh >> 4, h = bh & 15;
    const int n0 = blockIdx.x * 64;

    __shared__ float kvs[64][64];
    __shared__ float qs[64][64];
    __shared__ float ksums[64];
    __shared__ float dens[64];

    const int tid = threadIdx.x;

    // load kv[b,h] tile: 1024 float4
    {
        const float4* src = (const float4*)(g_kv + (size_t)bh * DK * DK);
        float4* dst = (float4*)kvs;
        for (int i = tid; i < 1024; i += 256) dst[i] = src[i];
    }
    // load 64 q rows (already activated): qs[r][c]
    for (int j = tid; j < 1024; j += 256) {
        const int r = j >> 4, c = j & 15;
        ((float4*)qs)[j] = *(const float4*)(g_qkv
            + (size_t)(b*SEQ + n0 + r) * QKVN + h*64 + c*4);
    }
    if (tid < 16)
        ((float4*)ksums)[tid] = *(const float4*)(g_ksum + bh*DK + tid*4);
    __syncthreads();

    if (tid < 64) {
        float s = 0.0f;
        #pragma unroll
        for (int dd = 0; dd < 64; ++dd) s += qs[tid][dd] * ksums[dd];
        dens[tid] = s + 1e-6f;
    }
    __syncthreads();

    const int rg = tid >> 4;       // row group: rows rg*4..+4
    const int f4 = tid & 15;       // f cols f4*4..+4
    float4 acc[4];
    #pragma unroll
    for (int r = 0; r < 4; ++r) acc[r] = make_float4(0.f,0.f,0.f,0.f);

    #pragma unroll 8
    for (int dd = 0; dd < 64; ++dd) {
        const float4 kvv = *(const float4*)&kvs[dd][f4*4];
        #pragma unroll
        for (int r = 0; r < 4; ++r) {
            const float qv = qs[rg*4 + r][dd];
            acc[r].x += qv * kvv.x; acc[r].y += qv * kvv.y;
            acc[r].z += qv * kvv.z; acc[r].w += qv * kvv.w;
        }
    }

    #pragma unroll
    for (int r = 0; r < 4; ++r) {
        const int row = n0 + rg*4 + r;
        const float inv = 1.0f / dens[rg*4 + r];
        float4 o;
        o.x = acc[r].x * inv; o.y = acc[r].y * inv;
        o.z = acc[r].z * inv; o.w = acc[r].w * inv;
        *(float4*)(g_attn + (size_t)(b*SEQ + row) * DMODEL + h*64 + f4*4) = o;
    }
}

// ---------------------------------------------------------------------------
extern "C" void kernel_launch(void* const* d_in, const int* in_sizes, int n_in,
                              void* d_out, int out_size)
{
    const float* x     = (const float*)d_in[0];
    const float* wqkv  = (const float*)d_in[1];
    const float* wo    = (const float*)d_in[2];
    float* out = (float*)d_out;

    float *qkv_p = nullptr, *attn_p = nullptr;
    cudaGetSymbolAddress((void**)&qkv_p,  g_qkv);
    cudaGetSymbolAddress((void**)&attn_p, g_attn);

    const int M = BATCH * SEQ;

    // 1) QKV projection + fused elu+1 on q,k columns
    sgemm_kernel<true><<<dim3(QKVN/128, M/128), 256>>>(x, wqkv, qkv_p, M, QKVN, DMODEL);

    // 2) zero kv/ksum accumulators (deterministic across graph replays)
    zero_kv_kernel<<<(BATCH*NH*DK*DK + 255)/256, 256>>>();

    // 3) kv = k^T v and k_sum reductions
    kv_kernel<<<dim3(BATCH*NH, 16), 256>>>();

    // 4) numerator / denominator -> attn
    attn_kernel<<<dim3(SEQ/64, BATCH*NH), 256>>>();

    // 5) output projection
    sgemm_kernel<false><<<dim3(DMODEL/128, M/128), 256>>>(attn_p, wo, out, M, DMODEL, DMODEL);
}

// round 3
// speedup vs baseline: 1.8585x; 1.8585x over previous
#include <cuda_runtime.h>
#include <cuda_bf16.h>
#include <cstdint>
#include <math.h>

#define BATCH 4
#define SEQ   8192
#define DMODEL 1024
#define NH    16
#define DK    64
#define QKVN  (3*DMODEL)
#define MTOT  (BATCH*SEQ)

// ---------------------------------------------------------------------------
// Scratch (__device__ globals; allocation-free rule)
// ---------------------------------------------------------------------------
__device__ float g_qkv[(size_t)MTOT*QKVN];              // fp32 qkv, q/k activated
__device__ __nv_bfloat16 g_xhi[(size_t)MTOT*DMODEL];    // x split
__device__ __nv_bfloat16 g_xlo[(size_t)MTOT*DMODEL];
__device__ __nv_bfloat16 g_ahi[(size_t)MTOT*DMODEL];    // attn split
__device__ __nv_bfloat16 g_alo[(size_t)MTOT*DMODEL];
__device__ __nv_bfloat16 g_wqh[(size_t)QKVN*DMODEL];    // w_qkv^T split [3072][1024]
__device__ __nv_bfloat16 g_wql[(size_t)QKVN*DMODEL];
__device__ __nv_bfloat16 g_woh[(size_t)DMODEL*DMODEL];  // w_o^T split [1024][1024]
__device__ __nv_bfloat16 g_wol[(size_t)DMODEL*DMODEL];
__device__ float g_kv[BATCH*NH*DK*DK];
__device__ float g_ksum[BATCH*NH*DK];

// ---------------------------------------------------------------------------
// Helpers (baseline PTX only: works at target sm_103 without 'a' suffix)
// ---------------------------------------------------------------------------
__device__ __forceinline__ uint32_t smem_u32(const void* p) {
    uint32_t a;
    asm("{ .reg .u64 t; cvta.to.shared.u64 t, %1; cvt.u32.u64 %0, t; }" : "=r"(a) : "l"(p));
    return a;
}
__device__ __forceinline__ void cp_async16(uint32_t saddr, const void* gaddr) {
    asm volatile("cp.async.cg.shared.global [%0], [%1], 16;" :: "r"(saddr), "l"(gaddr));
}
__device__ __forceinline__ void cp_commit() {
    asm volatile("cp.async.commit_group;" ::: "memory");
}
template<int N>
__device__ __forceinline__ void cp_wait() {
    asm volatile("cp.async.wait_group %0;" :: "n"(N) : "memory");
}
__device__ __forceinline__ void ldsm_x4(uint32_t* r, uint32_t addr) {
    asm volatile("ldmatrix.sync.aligned.m8n8.x4.shared.b16 {%0,%1,%2,%3}, [%4];"
        : "=r"(r[0]), "=r"(r[1]), "=r"(r[2]), "=r"(r[3]) : "r"(addr));
}
__device__ __forceinline__ void mma_bf16(float* c, const uint32_t* a, const uint32_t* b) {
    asm volatile(
        "mma.sync.aligned.m16n8k16.row.col.f32.bf16.bf16.f32 "
        "{%0,%1,%2,%3}, {%4,%5,%6,%7}, {%8,%9}, {%0,%1,%2,%3};"
        : "+f"(c[0]), "+f"(c[1]), "+f"(c[2]), "+f"(c[3])
        : "r"(a[0]), "r"(a[1]), "r"(a[2]), "r"(a[3]), "r"(b[0]), "r"(b[1]));
}

// ---------------------------------------------------------------------------
// Split fp32 -> bf16 hi/lo
// ---------------------------------------------------------------------------
__global__ void __launch_bounds__(256) split2_kernel(
    const float* __restrict__ src, __nv_bfloat16* __restrict__ hi,
    __nv_bfloat16* __restrict__ lo, int n4)
{
    int i = blockIdx.x * 256 + threadIdx.x;
    if (i >= n4) return;
    float4 v = ((const float4*)src)[i];
    ushort4 hv, lv;
    float* vp = &v.x;
    unsigned short* hp = &hv.x;
    unsigned short* lp = &lv.x;
    #pragma unroll
    for (int j = 0; j < 4; ++j) {
        __nv_bfloat16 h = __float2bfloat16(vp[j]);
        __nv_bfloat16 l = __float2bfloat16(vp[j] - __bfloat162float(h));
        hp[j] = __bfloat16_as_ushort(h);
        lp[j] = __bfloat16_as_ushort(l);
    }
    ((ushort4*)hi)[i] = hv;
    ((ushort4*)lo)[i] = lv;
}

// Transpose + split: w [K][N] fp32 -> wT hi/lo [N][K] bf16
__global__ void __launch_bounds__(256) tsplit_kernel(
    const float* __restrict__ w, __nv_bfloat16* __restrict__ hi,
    __nv_bfloat16* __restrict__ lo, int K, int N)
{
    int idx = blockIdx.x * 256 + threadIdx.x;
    if (idx >= K * N) return;
    int k = idx / N, n = idx - k * N;
    float v = w[idx];
    __nv_bfloat16 h = __float2bfloat16(v);
    __nv_bfloat16 l = __float2bfloat16(v - __bfloat162float(h));
    hi[(size_t)n * K + k] = h;
    lo[(size_t)n * K + k] = l;
}

// ---------------------------------------------------------------------------
// mma.sync split-bf16 GEMM: C[M,ldc] = A[M,K] @ B^T (B stored [N][K] K-major)
// BM=BN=128, BK=32, 256 threads (8 warps 4x2, 32x64 warp tiles),
// 4-stage cp.async pipeline, 80B-stride smem (conflict-free ldmatrix).
// ACT: elu(x)+1 on output cols < 2048.
// ---------------------------------------------------------------------------
#define RS 80                      // smem row stride bytes (64B data + 16B pad)
#define TILE_B (128*RS)            // 10240 B per operand tile
#define STAGE_B (4*TILE_B)         // Ahi|Alo|Bhi|Blo = 40960 B
#define NSTAGE 4
#define HS_TOTAL (NSTAGE*STAGE_B)  // 163840 B

template<bool ACT>
__global__ void __launch_bounds__(256, 1)
hmma_kernel(const __nv_bfloat16* __restrict__ Ahi, const __nv_bfloat16* __restrict__ Alo,
            const __nv_bfloat16* __restrict__ Bhi, const __nv_bfloat16* __restrict__ Blo,
            float* __restrict__ C, int ldc, int K)
{
    extern __shared__ __align__(128) char smem[];
    const uint32_t sbase = smem_u32(smem);
    const int tid = threadIdx.x;
    const int wid = tid >> 5, l = tid & 31;
    const int n0 = blockIdx.x * 128;
    const int m0 = blockIdx.y * 128;
    const int wm = (wid & 3) * 32;     // warp m offset
    const int wn = (wid >> 2) * 64;    // warp n offset

    // global row pointers (bytes) for the loader
    const int lrow = tid >> 1;          // 0..127
    const int lcb  = (tid & 1) * 32;    // 0 or 32 bytes within 64B k-slice
    const char* gA[4];
    gA[0] = (const char*)(Ahi + (size_t)(m0 + lrow) * K);
    gA[1] = (const char*)(Alo + (size_t)(m0 + lrow) * K);
    gA[2] = (const char*)(Bhi + (size_t)(n0 + lrow) * K);
    gA[3] = (const char*)(Blo + (size_t)(n0 + lrow) * K);
    const uint32_t sdst = sbase + lrow * RS + lcb;

    const int nkt = K >> 5;             // 32-element k chunks

    // issue loads for stage s covering k-chunk kt
    auto load_stage = [&](int kt) {
        const int buf = kt & (NSTAGE - 1);
        const uint32_t sb = sdst + buf * STAGE_B;
        const int goff = kt * 64;       // bytes along K
        #pragma unroll
        for (int t = 0; t < 4; ++t) {
            cp_async16(sb + t * TILE_B,      gA[t] + goff + lcb);
            cp_async16(sb + t * TILE_B + 16, gA[t] + goff + lcb + 16);
        }
    };

    #pragma unroll
    for (int s = 0; s < NSTAGE - 1; ++s) { load_stage(s); cp_commit(); }

    float acc[16][4];
    #pragma unroll
    for (int i = 0; i < 16; ++i)
        #pragma unroll
        for (int j = 0; j < 4; ++j) acc[i][j] = 0.0f;

    // ldmatrix lane addressing (constant per thread)
    const uint32_t a_off = (uint32_t)((wm + (l & 15)) * RS + ((l >> 4) * 16));
    const uint32_t b_off = (uint32_t)((wn + ((l >> 4) & 1) * 8 + (l & 7)) * RS
                                       + (((l >> 3) & 1) * 16));

    #pragma unroll 1
    for (int kt = 0; kt < nkt; ++kt) {
        cp_wait<NSTAGE - 2>();
        __syncthreads();
        const uint32_t sb = sbase + (kt & (NSTAGE - 1)) * STAGE_B;

        #pragma unroll
        for (int kk = 0; kk < 2; ++kk) {
            const uint32_t ko = kk * 32;
            uint32_t ah[2][4], al[2][4], bh[4][4], bl[4][4];
            #pragma unroll
            for (int mt = 0; mt < 2; ++mt) {
                ldsm_x4(ah[mt], sb + 0*TILE_B + a_off + mt * (16*RS) + ko);
                ldsm_x4(al[mt], sb + 1*TILE_B + a_off + mt * (16*RS) + ko);
            }
            #pragma unroll
            for (int ng = 0; ng < 4; ++ng) {
                ldsm_x4(bh[ng], sb + 2*TILE_B + b_off + ng * (16*RS) + ko);
                ldsm_x4(bl[ng], sb + 3*TILE_B + b_off + ng * (16*RS) + ko);
            }
            #pragma unroll
            for (int mt = 0; mt < 2; ++mt)
                #pragma unroll
                for (int nt = 0; nt < 8; ++nt) {
                    float* c = acc[mt * 8 + nt];
                    const uint32_t* bhp = &bh[nt >> 1][(nt & 1) * 2];
                    const uint32_t* blp = &bl[nt >> 1][(nt & 1) * 2];
                    mma_bf16(c, ah[mt], bhp);
                    mma_bf16(c, ah[mt], blp);
                    mma_bf16(c, al[mt], bhp);
                }
        }
        __syncthreads();
        if (kt + NSTAGE - 1 < nkt) load_stage(kt + NSTAGE - 1);
        cp_commit();
    }

    // epilogue: direct float2 stores (+ optional elu+1)
    const bool doact = ACT && (n0 < 2048);
    const int erow = m0 + wm + (l >> 2);
    const int ecol = n0 + wn + (l & 3) * 2;
    #pragma unroll
    for (int mt = 0; mt < 2; ++mt)
        #pragma unroll
        for (int nt = 0; nt < 8; ++nt) {
            float v0 = acc[mt*8+nt][0], v1 = acc[mt*8+nt][1];
            float v2 = acc[mt*8+nt][2], v3 = acc[mt*8+nt][3];
            if (doact) {
                v0 = (v0 > 0.f) ? v0 + 1.f : expf(v0);
                v1 = (v1 > 0.f) ? v1 + 1.f : expf(v1);
                v2 = (v2 > 0.f) ? v2 + 1.f : expf(v2);
                v3 = (v3 > 0.f) ? v3 + 1.f : expf(v3);
            }
            float2 o0; o0.x = v0; o0.y = v1;
            float2 o1; o1.x = v2; o1.y = v3;
            const int r = erow + mt * 16;
            const int cc = ecol + nt * 8;
            *(float2*)(C + (size_t)r * ldc + cc) = o0;
            *(float2*)(C + (size_t)(r + 8) * ldc + cc) = o1;
        }
}

// ---------------------------------------------------------------------------
// Zero kv/ksum accumulators
// ---------------------------------------------------------------------------
__global__ void zero_kv_kernel() {
    int i = blockIdx.x * 256 + threadIdx.x;
    if (i < BATCH*NH*DK*DK) g_kv[i] = 0.0f;
    if (i < BATCH*NH*DK)    g_ksum[i] = 0.0f;
}

// ---------------------------------------------------------------------------
// kv[b,h,d,f] = sum_n k[b,n,h,d] * v[b,n,h,f];  ksum[b,h,d] = sum_n k
// ---------------------------------------------------------------------------
__global__ void __launch_bounds__(256) kv_kernel() {
    const int bh = blockIdx.x;
    const int b  = bh >> 4, h = bh & 15;
    const int n0 = blockIdx.y * 512;

    __shared__ float ks[8][64];
    __shared__ float vs[8][64];

    const int tid = threadIdx.x;
    const int d   = tid & 63;
    const int fg  = tid >> 6;
    const int rr   = tid >> 5;
    const int half = (tid >> 4) & 1;
    const int c4   = tid & 15;

    float4 acc[4];
    #pragma unroll
    for (int i = 0; i < 4; ++i) acc[i] = make_float4(0.f,0.f,0.f,0.f);
    float ksacc = 0.0f;

    for (int r0 = 0; r0 < 512; r0 += 8) {
        const size_t rowbase = (size_t)(b*SEQ + n0 + r0 + rr) * QKVN;
        const float4 val = *(const float4*)(g_qkv + rowbase
                            + (half ? 2048 : 1024) + h*64 + c4*4);
        __syncthreads();
        if (half == 0) *(float4*)&ks[rr][c4*4] = val;
        else           *(float4*)&vs[rr][c4*4] = val;
        __syncthreads();
        #pragma unroll
        for (int r = 0; r < 8; ++r) {
            const float kd = ks[r][d];
            ksacc += kd;
            #pragma unroll
            for (int i4 = 0; i4 < 4; ++i4) {
                const float4 vv = *(const float4*)&vs[r][fg*16 + i4*4];
                acc[i4].x += kd * vv.x; acc[i4].y += kd * vv.y;
                acc[i4].z += kd * vv.z; acc[i4].w += kd * vv.w;
            }
        }
    }

    float* dst = g_kv + ((size_t)bh * DK + d) * DK + fg*16;
    #pragma unroll
    for (int i4 = 0; i4 < 4; ++i4) {
        atomicAdd(dst + i4*4 + 0, acc[i4].x);
        atomicAdd(dst + i4*4 + 1, acc[i4].y);
        atomicAdd(dst + i4*4 + 2, acc[i4].z);
        atomicAdd(dst + i4*4 + 3, acc[i4].w);
    }
    if (fg == 0) atomicAdd(&g_ksum[bh*DK + d], ksacc);
}

// ---------------------------------------------------------------------------
// attn = (q @ kv) / (q . ksum + 1e-6), output split to bf16 hi/lo
// ---------------------------------------------------------------------------
__global__ void __launch_bounds__(256) attn_kernel() {
    const int bh = blockIdx.y;
    const int b  = bh >> 4, hh = bh & 15;
    const int n0 = blockIdx.x * 64;

    __shared__ float kvs[64][64];
    __shared__ float qs[64][64];
    __shared__ float ksums[64];
    __shared__ float dens[64];

    const int tid = threadIdx.x;

    {
        const float4* src = (const float4*)(g_kv + (size_t)bh * DK * DK);
        float4* dst = (float4*)kvs;
        for (int i = tid; i < 1024; i += 256) dst[i] = src[i];
    }
    for (int j = tid; j < 1024; j += 256) {
        const int r = j >> 4, c = j & 15;
        ((float4*)qs)[j] = *(const float4*)(g_qkv
            + (size_t)(b*SEQ + n0 + r) * QKVN + hh*64 + c*4);
    }
    if (tid < 16)
        ((float4*)ksums)[tid] = *(const float4*)(g_ksum + bh*DK + tid*4);
    __syncthreads();

    if (tid < 64) {
        float s = 0.0f;
        #pragma unroll
        for (int dd = 0; dd < 64; ++dd) s += qs[tid][dd] * ksums[dd];
        dens[tid] = s + 1e-6f;
    }
    __syncthreads();

    const int rg = tid >> 4;
    const int f4 = tid & 15;
    float4 acc[4];
    #pragma unroll
    for (int r = 0; r < 4; ++r) acc[r] = make_float4(0.f,0.f,0.f,0.f);

    #pragma unroll 8
    for (int dd = 0; dd < 64; ++dd) {
        const float4 kvv = *(const float4*)&kvs[dd][f4*4];
        #pragma unroll
        for (int r = 0; r < 4; ++r) {
            const float qv = qs[rg*4 + r][dd];
            acc[r].x += qv * kvv.x; acc[r].y += qv * kvv.y;
            acc[r].z += qv * kvv.z; acc[r].w += qv * kvv.w;
        }
    }

    #pragma unroll
    for (int r = 0; r < 4; ++r) {
        const int row = n0 + rg*4 + r;
        const float inv = 1.0f / dens[rg*4 + r];
        float o[4];
        o[0] = acc[r].x * inv; o[1] = acc[r].y * inv;
        o[2] = acc[r].z * inv; o[3] = acc[r].w * inv;
        ushort4 hv, lv;
        unsigned short* hp = &hv.x;
        unsigned short* lp = &lv.x;
        #pragma unroll
        for (int j = 0; j < 4; ++j) {
            __nv_bfloat16 hbf = __float2bfloat16(o[j]);
            __nv_bfloat16 lbf = __float2bfloat16(o[j] - __bfloat162float(hbf));
            hp[j] = __bfloat16_as_ushort(hbf);
            lp[j] = __bfloat16_as_ushort(lbf);
        }
        const size_t idx = ((size_t)(b*SEQ + row) * DMODEL + hh*64 + f4*4) >> 2;
        ((ushort4*)g_ahi)[idx] = hv;
        ((ushort4*)g_alo)[idx] = lv;
    }
}

// ---------------------------------------------------------------------------
extern "C" void kernel_launch(void* const* d_in, const int* in_sizes, int n_in,
                              void* d_out, int out_size)
{
    const float* x    = (const float*)d_in[0];
    const float* wqkv = (const float*)d_in[1];
    const float* wo   = (const float*)d_in[2];
    float* out = (float*)d_out;

    float *qkv_p = nullptr;
    __nv_bfloat16 *xhi, *xlo, *ahi, *alo, *wqh, *wql, *woh, *wol;
    cudaGetSymbolAddress((void**)&qkv_p, g_qkv);
    cudaGetSymbolAddress((void**)&xhi, g_xhi);
    cudaGetSymbolAddress((void**)&xlo, g_xlo);
    cudaGetSymbolAddress((void**)&ahi, g_ahi);
    cudaGetSymbolAddress((void**)&alo, g_alo);
    cudaGetSymbolAddress((void**)&wqh, g_wqh);
    cudaGetSymbolAddress((void**)&wql, g_wql);
    cudaGetSymbolAddress((void**)&woh, g_woh);
    cudaGetSymbolAddress((void**)&wol, g_wol);

    cudaFuncSetAttribute(hmma_kernel<true>,
        cudaFuncAttributeMaxDynamicSharedMemorySize, HS_TOTAL);
    cudaFuncSetAttribute(hmma_kernel<false>,
        cudaFuncAttributeMaxDynamicSharedMemorySize, HS_TOTAL);

    // 1) split inputs
    {
        int n4 = MTOT * DMODEL / 4;
        split2_kernel<<<(n4 + 255)/256, 256>>>(x, xhi, xlo, n4);
    }
    tsplit_kernel<<<(DMODEL*QKVN + 255)/256, 256>>>(wqkv, wqh, wql, DMODEL, QKVN);
    tsplit_kernel<<<(DMODEL*DMODEL + 255)/256, 256>>>(wo, woh, wol, DMODEL, DMODEL);

    // 2) QKV projection (mma.sync bf16 split) + fused elu+1 on q,k columns
    hmma_kernel<true><<<dim3(QKVN/128, MTOT/128), 256, HS_TOTAL>>>(
        xhi, xlo, wqh, wql, qkv_p, QKVN, DMODEL);

    // 3) zero accumulators
    zero_kv_kernel<<<(BATCH*NH*DK*DK + 255)/256, 256>>>();

    // 4) kv / ksum reductions
    kv_kernel<<<dim3(BATCH*NH, 16), 256>>>();

    // 5) attn (outputs bf16 hi/lo)
    attn_kernel<<<dim3(SEQ/64, BATCH*NH), 256>>>();

    // 6) output projection (mma.sync bf16 split)
    hmma_kernel<false><<<dim3(DMODEL/128, MTOT/128), 256, HS_TOTAL>>>(
        ahi, alo, woh, wol, out, DMODEL, DMODEL);
}

// round 4
// speedup vs baseline: 2.3176x; 1.2470x over previous
#include <cuda_runtime.h>
#include <cuda_bf16.h>
#include <cstdint>
#include <math.h>

#define BATCH 4
#define SEQ   8192
#define DMODEL 1024
#define NH    16
#define DK    64
#define QKVN  (3*DMODEL)
#define MTOT  (BATCH*SEQ)

// ---------------------------------------------------------------------------
// Scratch (__device__ globals; allocation-free rule)
// ---------------------------------------------------------------------------
__device__ float g_qkv[(size_t)MTOT*QKVN];              // fp32 qkv, q/k activated
__device__ __nv_bfloat16 g_xhi[(size_t)MTOT*DMODEL];    // x split
__device__ __nv_bfloat16 g_xlo[(size_t)MTOT*DMODEL];
__device__ __nv_bfloat16 g_ahi[(size_t)MTOT*DMODEL];    // attn split
__device__ __nv_bfloat16 g_alo[(size_t)MTOT*DMODEL];
__device__ __nv_bfloat16 g_wqh[(size_t)QKVN*DMODEL];    // w_qkv^T split [3072][1024]
__device__ __nv_bfloat16 g_wql[(size_t)QKVN*DMODEL];
__device__ __nv_bfloat16 g_woh[(size_t)DMODEL*DMODEL];  // w_o^T split [1024][1024]
__device__ __nv_bfloat16 g_wol[(size_t)DMODEL*DMODEL];
__device__ float g_kv[BATCH*NH*DK*DK];
__device__ float g_ksum[BATCH*NH*DK];

// ---------------------------------------------------------------------------
// Helpers (baseline PTX only: must assemble at target sm_103, no 'a' features)
// ---------------------------------------------------------------------------
__device__ __forceinline__ uint32_t smem_u32(const void* p) {
    uint32_t a;
    asm("{ .reg .u64 t; cvta.to.shared.u64 t, %1; cvt.u32.u64 %0, t; }" : "=r"(a) : "l"(p));
    return a;
}
__device__ __forceinline__ void cp_async16(uint32_t saddr, const void* gaddr) {
    asm volatile("cp.async.cg.shared.global [%0], [%1], 16;" :: "r"(saddr), "l"(gaddr));
}
__device__ __forceinline__ void cp_commit() {
    asm volatile("cp.async.commit_group;" ::: "memory");
}
template<int N>
__device__ __forceinline__ void cp_wait() {
    asm volatile("cp.async.wait_group %0;" :: "n"(N) : "memory");
}
__device__ __forceinline__ void ldsm_x4(uint32_t* r, uint32_t addr) {
    asm volatile("ldmatrix.sync.aligned.m8n8.x4.shared.b16 {%0,%1,%2,%3}, [%4];"
        : "=r"(r[0]), "=r"(r[1]), "=r"(r[2]), "=r"(r[3]) : "r"(addr));
}
__device__ __forceinline__ void mma_bf16(float* c, const uint32_t* a, const uint32_t* b) {
    asm volatile(
        "mma.sync.aligned.m16n8k16.row.col.f32.bf16.bf16.f32 "
        "{%0,%1,%2,%3}, {%4,%5,%6,%7}, {%8,%9}, {%0,%1,%2,%3};"
        : "+f"(c[0]), "+f"(c[1]), "+f"(c[2]), "+f"(c[3])
        : "r"(a[0]), "r"(a[1]), "r"(a[2]), "r"(a[3]), "r"(b[0]), "r"(b[1]));
}

// ---------------------------------------------------------------------------
// Split fp32 -> bf16 hi/lo
// ---------------------------------------------------------------------------
__global__ void __launch_bounds__(256) split2_kernel(
    const float* __restrict__ src, __nv_bfloat16* __restrict__ hi,
    __nv_bfloat16* __restrict__ lo, int n4)
{
    int i = blockIdx.x * 256 + threadIdx.x;
    if (i >= n4) return;
    float4 v = ((const float4*)src)[i];
    ushort4 hv, lv;
    float* vp = &v.x;
    unsigned short* hp = &hv.x;
    unsigned short* lp = &lv.x;
    #pragma unroll
    for (int j = 0; j < 4; ++j) {
        __nv_bfloat16 h = __float2bfloat16(vp[j]);
        __nv_bfloat16 l = __float2bfloat16(vp[j] - __bfloat162float(h));
        hp[j] = __bfloat16_as_ushort(h);
        lp[j] = __bfloat16_as_ushort(l);
    }
    ((ushort4*)hi)[i] = hv;
    ((ushort4*)lo)[i] = lv;
}

// Transpose + split: w [K][N] fp32 -> wT hi/lo [N][K] bf16
__global__ void __launch_bounds__(256) tsplit_kernel(
    const float* __restrict__ w, __nv_bfloat16* __restrict__ hi,
    __nv_bfloat16* __restrict__ lo, int K, int N)
{
    int idx = blockIdx.x * 256 + threadIdx.x;
    if (idx >= K * N) return;
    int k = idx / N, n = idx - k * N;
    float v = w[idx];
    __nv_bfloat16 h = __float2bfloat16(v);
    __nv_bfloat16 l = __float2bfloat16(v - __bfloat162float(h));
    hi[(size_t)n * K + k] = h;
    lo[(size_t)n * K + k] = l;
}

// ---------------------------------------------------------------------------
// mma.sync split-bf16 GEMM: C[M,ldc] = A[M,K] @ B^T (B stored [N][K] K-major)
// BM=BN=128, BK=32, 256 threads (8 warps 4x2, 32x64 warp tiles),
// 3-stage cp.async pipeline, padding-free XOR-swizzled smem (2 CTAs/SM).
// Swizzle: 64B rows of 4x16B chunks; phys_chunk = chunk ^ ((row>>1)&3).
// ACT: elu(x)+1 on output cols < 2048.
// ---------------------------------------------------------------------------
#define TILE_B (128*64)            // 8192 B per operand tile
#define STAGE_B (4*TILE_B)         // Ahi|Alo|Bhi|Blo = 32768 B
#define NSTAGE 3
#define HS_TOTAL (NSTAGE*STAGE_B)  // 98304 B

template<bool ACT>
__global__ void __launch_bounds__(256, 2)
hmma_kernel(const __nv_bfloat16* __restrict__ Ahi, const __nv_bfloat16* __restrict__ Alo,
            const __nv_bfloat16* __restrict__ Bhi, const __nv_bfloat16* __restrict__ Blo,
            float* __restrict__ C, int ldc, int K)
{
    extern __shared__ __align__(128) char smem[];
    const uint32_t sbase = smem_u32(smem);
    const int tid = threadIdx.x;
    const int wid = tid >> 5, l = tid & 31;
    const int n0 = blockIdx.x * 128;
    const int m0 = blockIdx.y * 128;
    const int wm = (wid & 3) * 32;     // warp m offset
    const int wn = (wid >> 2) * 64;    // warp n offset

    // ---- loader mapping: thread -> (row, 32B chunk-pair), swizzled dest ----
    const int lrow = tid >> 1;          // 0..127
    const int c0   = (tid & 1) * 2;     // logical chunk 0 or 2
    const int lsw  = (lrow >> 1) & 3;   // swizzle key
    const char* gA[4];
    gA[0] = (const char*)(Ahi + (size_t)(m0 + lrow) * K);
    gA[1] = (const char*)(Alo + (size_t)(m0 + lrow) * K);
    gA[2] = (const char*)(Bhi + (size_t)(n0 + lrow) * K);
    gA[3] = (const char*)(Blo + (size_t)(n0 + lrow) * K);
    const uint32_t sd0 = sbase + lrow * 64 + (uint32_t)((c0 ^ lsw) << 4);
    const uint32_t sd1 = sbase + lrow * 64 + (uint32_t)(((c0 + 1) ^ lsw) << 4);

    const int nkt = K >> 5;             // 32-element k chunks

    auto load_stage = [&](int kt) {
        const int buf = kt % NSTAGE;
        const uint32_t b0 = sd0 + buf * STAGE_B;
        const uint32_t b1 = sd1 + buf * STAGE_B;
        const int goff = kt * 64;       // bytes along K
        #pragma unroll
        for (int t = 0; t < 4; ++t) {
            cp_async16(b0 + t * TILE_B, gA[t] + goff + c0 * 16);
            cp_async16(b1 + t * TILE_B, gA[t] + goff + c0 * 16 + 16);
        }
    };

    #pragma unroll
    for (int s = 0; s < NSTAGE - 1; ++s) { load_stage(s); cp_commit(); }

    float acc[16][4];
    #pragma unroll
    for (int i = 0; i < 16; ++i)
        #pragma unroll
        for (int j = 0; j < 4; ++j) acc[i][j] = 0.0f;

    // ---- ldmatrix lane addressing (row base + swizzle key per fragment) ----
    uint32_t offA[2], swA[2];
    #pragma unroll
    for (int mt = 0; mt < 2; ++mt) {
        const int r = wm + (l & 15) + mt * 16;
        offA[mt] = (uint32_t)(r * 64);
        swA[mt]  = (uint32_t)((r >> 1) & 3);
    }
    uint32_t offB[4], swB[4];
    #pragma unroll
    for (int ng = 0; ng < 4; ++ng) {
        const int r = wn + ((l >> 4) & 1) * 8 + (l & 7) + ng * 16;
        offB[ng] = (uint32_t)(r * 64);
        swB[ng]  = (uint32_t)((r >> 1) & 3);
    }
    const uint32_t caA = (uint32_t)(l >> 4);        // A logical sub-chunk
    const uint32_t caB = (uint32_t)((l >> 3) & 1);  // B logical sub-chunk

    #pragma unroll 1
    for (int kt = 0; kt < nkt; ++kt) {
        cp_wait<NSTAGE - 2>();
        __syncthreads();
        const uint32_t sb = sbase + (kt % NSTAGE) * STAGE_B;

        #pragma unroll
        for (int kk = 0; kk < 2; ++kk) {
            const uint32_t ccA = kk * 2 + caA;     // logical chunk 0..3
            const uint32_t ccB = kk * 2 + caB;
            uint32_t ah[2][4], al[2][4], bh[4][4], bl[4][4];
            #pragma unroll
            for (int mt = 0; mt < 2; ++mt) {
                const uint32_t ao = offA[mt] + ((ccA ^ swA[mt]) << 4);
                ldsm_x4(ah[mt], sb + 0*TILE_B + ao);
                ldsm_x4(al[mt], sb + 1*TILE_B + ao);
            }
            #pragma unroll
            for (int ng = 0; ng < 4; ++ng) {
                const uint32_t bo = offB[ng] + ((ccB ^ swB[ng]) << 4);
                ldsm_x4(bh[ng], sb + 2*TILE_B + bo);
                ldsm_x4(bl[ng], sb + 3*TILE_B + bo);
            }
            #pragma unroll
            for (int mt = 0; mt < 2; ++mt)
                #pragma unroll
                for (int nt = 0; nt < 8; ++nt) {
                    float* c = acc[mt * 8 + nt];
                    const uint32_t* bhp = &bh[nt >> 1][(nt & 1) * 2];
                    const uint32_t* blp = &bl[nt >> 1][(nt & 1) * 2];
                    mma_bf16(c, ah[mt], bhp);
                    mma_bf16(c, ah[mt], blp);
                    mma_bf16(c, al[mt], bhp);
                }
        }
        __syncthreads();
        if (kt + NSTAGE - 1 < nkt) load_stage(kt + NSTAGE - 1);
        cp_commit();
    }

    // epilogue: direct float2 stores (+ optional elu+1)
    const bool doact = ACT && (n0 < 2048);
    const int erow = m0 + wm + (l >> 2);
    const int ecol = n0 + wn + (l & 3) * 2;
    #pragma unroll
    for (int mt = 0; mt < 2; ++mt)
        #pragma unroll
        for (int nt = 0; nt < 8; ++nt) {
            float v0 = acc[mt*8+nt][0], v1 = acc[mt*8+nt][1];
            float v2 = acc[mt*8+nt][2], v3 = acc[mt*8+nt][3];
            if (doact) {
                v0 = (v0 > 0.f) ? v0 + 1.f : expf(v0);
                v1 = (v1 > 0.f) ? v1 + 1.f : expf(v1);
                v2 = (v2 > 0.f) ? v2 + 1.f : expf(v2);
                v3 = (v3 > 0.f) ? v3 + 1.f : expf(v3);
            }
            float2 o0; o0.x = v0; o0.y = v1;
            float2 o1; o1.x = v2; o1.y = v3;
            const int r = erow + mt * 16;
            const int cc = ecol + nt * 8;
            *(float2*)(C + (size_t)r * ldc + cc) = o0;
            *(float2*)(C + (size_t)(r + 8) * ldc + cc) = o1;
        }
}

// ---------------------------------------------------------------------------
// Zero kv/ksum accumulators
// ---------------------------------------------------------------------------
__global__ void zero_kv_kernel() {
    int i = blockIdx.x * 256 + threadIdx.x;
    if (i < BATCH*NH*DK*DK) g_kv[i] = 0.0f;
    if (i < BATCH*NH*DK)    g_ksum[i] = 0.0f;
}

// ---------------------------------------------------------------------------
// kv[b,h,d,f] = sum_n k[b,n,h,d] * v[b,n,h,f];  ksum[b,h,d] = sum_n k
// ---------------------------------------------------------------------------
__global__ void __launch_bounds__(256) kv_kernel() {
    const int bh = blockIdx.x;
    const int b  = bh >> 4, h = bh & 15;
    const int n0 = blockIdx.y * 512;

    __shared__ float ks[8][64];
    __shared__ float vs[8][64];

    const int tid = threadIdx.x;
    const int d   = tid & 63;
    const int fg  = tid >> 6;
    const int rr   = tid >> 5;
    const int half = (tid >> 4) & 1;
    const int c4   = tid & 15;

    float4 acc[4];
    #pragma unroll
    for (int i = 0; i < 4; ++i) acc[i] = make_float4(0.f,0.f,0.f,0.f);
    float ksacc = 0.0f;

    for (int r0 = 0; r0 < 512; r0 += 8) {
        const size_t rowbase = (size_t)(b*SEQ + n0 + r0 + rr) * QKVN;
        const float4 val = *(const float4*)(g_qkv + rowbase
                            + (half ? 2048 : 1024) + h*64 + c4*4);
        __syncthreads();
        if (half == 0) *(float4*)&ks[rr][c4*4] = val;
        else           *(float4*)&vs[rr][c4*4] = val;
        __syncthreads();
        #pragma unroll
        for (int r = 0; r < 8; ++r) {
            const float kd = ks[r][d];
            ksacc += kd;
            #pragma unroll
            for (int i4 = 0; i4 < 4; ++i4) {
                const float4 vv = *(const float4*)&vs[r][fg*16 + i4*4];
                acc[i4].x += kd * vv.x; acc[i4].y += kd * vv.y;
                acc[i4].z += kd * vv.z; acc[i4].w += kd * vv.w;
            }
        }
    }

    float* dst = g_kv + ((size_t)bh * DK + d) * DK + fg*16;
    #pragma unroll
    for (int i4 = 0; i4 < 4; ++i4) {
        atomicAdd(dst + i4*4 + 0, acc[i4].x);
        atomicAdd(dst + i4*4 + 1, acc[i4].y);
        atomicAdd(dst + i4*4 + 2, acc[i4].z);
        atomicAdd(dst + i4*4 + 3, acc[i4].w);
    }
    if (fg == 0) atomicAdd(&g_ksum[bh*DK + d], ksacc);
}

// ---------------------------------------------------------------------------
// attn = (q @ kv) / (q . ksum + 1e-6), output split to bf16 hi/lo
// ---------------------------------------------------------------------------
__global__ void __launch_bounds__(256) attn_kernel() {
    const int bh = blockIdx.y;
    const int b  = bh >> 4, hh = bh & 15;
    const int n0 = blockIdx.x * 64;

    __shared__ float kvs[64][64];
    __shared__ float qs[64][64];
    __shared__ float ksums[64];
    __shared__ float dens[64];

    const int tid = threadIdx.x;

    {
        const float4* src = (const float4*)(g_kv + (size_t)bh * DK * DK);
        float4* dst = (float4*)kvs;
        for (int i = tid; i < 1024; i += 256) dst[i] = src[i];
    }
    for (int j = tid; j < 1024; j += 256) {
        const int r = j >> 4, c = j & 15;
        ((float4*)qs)[j] = *(const float4*)(g_qkv
            + (size_t)(b*SEQ + n0 + r) * QKVN + hh*64 + c*4);
    }
    if (tid < 16)
        ((float4*)ksums)[tid] = *(const float4*)(g_ksum + bh*DK + tid*4);
    __syncthreads();

    if (tid < 64) {
        float s = 0.0f;
        #pragma unroll
        for (int dd = 0; dd < 64; ++dd) s += qs[tid][dd] * ksums[dd];
        dens[tid] = s + 1e-6f;
    }
    __syncthreads();

    const int rg = tid >> 4;
    const int f4 = tid & 15;
    float4 acc[4];
    #pragma unroll
    for (int r = 0; r < 4; ++r) acc[r] = make_float4(0.f,0.f,0.f,0.f);

    #pragma unroll 8
    for (int dd = 0; dd < 64; ++dd) {
        const float4 kvv = *(const float4*)&kvs[dd][f4*4];
        #pragma unroll
        for (int r = 0; r < 4; ++r) {
            const float qv = qs[rg*4 + r][dd];
            acc[r].x += qv * kvv.x; acc[r].y += qv * kvv.y;
            acc[r].z += qv * kvv.z; acc[r].w += qv * kvv.w;
        }
    }

    #pragma unroll
    for (int r = 0; r < 4; ++r) {
        const int row = n0 + rg*4 + r;
        const float inv = 1.0f / dens[rg*4 + r];
        float o[4];
        o[0] = acc[r].x * inv; o[1] = acc[r].y * inv;
        o[2] = acc[r].z * inv; o[3] = acc[r].w * inv;
        ushort4 hv, lv;
        unsigned short* hp = &hv.x;
        unsigned short* lp = &lv.x;
        #pragma unroll
        for (int j = 0; j < 4; ++j) {
            __nv_bfloat16 hbf = __float2bfloat16(o[j]);
            __nv_bfloat16 lbf = __float2bfloat16(o[j] - __bfloat162float(hbf));
            hp[j] = __bfloat16_as_ushort(hbf);
            lp[j] = __bfloat16_as_ushort(lbf);
        }
        const size_t idx = ((size_t)(b*SEQ + row) * DMODEL + hh*64 + f4*4) >> 2;
        ((ushort4*)g_ahi)[idx] = hv;
        ((ushort4*)g_alo)[idx] = lv;
    }
}

// ---------------------------------------------------------------------------
extern "C" void kernel_launch(void* const* d_in, const int* in_sizes, int n_in,
                              void* d_out, int out_size)
{
    const float* x    = (const float*)d_in[0];
    const float* wqkv = (const float*)d_in[1];
    const float* wo   = (const float*)d_in[2];
    float* out = (float*)d_out;

    float *qkv_p = nullptr;
    __nv_bfloat16 *xhi, *xlo, *ahi, *alo, *wqh, *wql, *woh, *wol;
    cudaGetSymbolAddress((void**)&qkv_p, g_qkv);
    cudaGetSymbolAddress((void**)&xhi, g_xhi);
    cudaGetSymbolAddress((void**)&xlo, g_xlo);
    cudaGetSymbolAddress((void**)&ahi, g_ahi);
    cudaGetSymbolAddress((void**)&alo, g_alo);
    cudaGetSymbolAddress((void**)&wqh, g_wqh);
    cudaGetSymbolAddress((void**)&wql, g_wql);
    cudaGetSymbolAddress((void**)&woh, g_woh);
    cudaGetSymbolAddress((void**)&wol, g_wol);

    cudaFuncSetAttribute(hmma_kernel<true>,
        cudaFuncAttributeMaxDynamicSharedMemorySize, HS_TOTAL);
    cudaFuncSetAttribute(hmma_kernel<false>,
        cudaFuncAttributeMaxDynamicSharedMemorySize, HS_TOTAL);

    // 1) split inputs
    {
        int n4 = MTOT * DMODEL / 4;
        split2_kernel<<<(n4 + 255)/256, 256>>>(x, xhi, xlo, n4);
    }
    tsplit_kernel<<<(DMODEL*QKVN + 255)/256, 256>>>(wqkv, wqh, wql, DMODEL, QKVN);
    tsplit_kernel<<<(DMODEL*DMODEL + 255)/256, 256>>>(wo, woh, wol, DMODEL, DMODEL);

    // 2) QKV projection (mma.sync bf16 split) + fused elu+1 on q,k columns
    hmma_kernel<true><<<dim3(QKVN/128, MTOT/128), 256, HS_TOTAL>>>(
        xhi, xlo, wqh, wql, qkv_p, QKVN, DMODEL);

    // 3) zero accumulators
    zero_kv_kernel<<<(BATCH*NH*DK*DK + 255)/256, 256>>>();

    // 4) kv / ksum reductions
    kv_kernel<<<dim3(BATCH*NH, 16), 256>>>();

    // 5) attn (outputs bf16 hi/lo)
    attn_kernel<<<dim3(SEQ/64, BATCH*NH), 256>>>();

    // 6) output projection (mma.sync bf16 split)
    hmma_kernel<false><<<dim3(DMODEL/128, MTOT/128), 256, HS_TOTAL>>>(
        ahi, alo, woh, wol, out, DMODEL, DMODEL);
}

// round 5
// speedup vs baseline: 2.4117x; 1.0406x over previous
#include <cuda_runtime.h>
#include <cuda_bf16.h>
#include <cstdint>
#include <math.h>

#define BATCH 4
#define SEQ   8192
#define DMODEL 1024
#define NH    16
#define DK    64
#define QKVN  (3*DMODEL)
#define MTOT  (BATCH*SEQ)

// ---------------------------------------------------------------------------
// Scratch (__device__ globals; allocation-free rule)
// ---------------------------------------------------------------------------
__device__ float g_qkv[(size_t)MTOT*QKVN];              // fp32 qkv, q/k activated
__device__ __nv_bfloat16 g_xhi[(size_t)MTOT*DMODEL];    // x split
__device__ __nv_bfloat16 g_xlo[(size_t)MTOT*DMODEL];
__device__ __nv_bfloat16 g_ahi[(size_t)MTOT*DMODEL];    // attn split
__device__ __nv_bfloat16 g_alo[(size_t)MTOT*DMODEL];
__device__ __nv_bfloat16 g_wqh[(size_t)QKVN*DMODEL];    // w_qkv^T split [3072][1024]
__device__ __nv_bfloat16 g_wql[(size_t)QKVN*DMODEL];
__device__ __nv_bfloat16 g_woh[(size_t)DMODEL*DMODEL];  // w_o^T split [1024][1024]
__device__ __nv_bfloat16 g_wol[(size_t)DMODEL*DMODEL];
__device__ float g_kv[BATCH*NH*DK*DK];
__device__ float g_ksum[BATCH*NH*DK];

// ---------------------------------------------------------------------------
// Helpers (baseline PTX only: must assemble at target sm_103, no 'a' features)
// ---------------------------------------------------------------------------
__device__ __forceinline__ uint32_t smem_u32(const void* p) {
    uint32_t a;
    asm("{ .reg .u64 t; cvta.to.shared.u64 t, %1; cvt.u32.u64 %0, t; }" : "=r"(a) : "l"(p));
    return a;
}
__device__ __forceinline__ void cp_async16(uint32_t saddr, const void* gaddr) {
    asm volatile("cp.async.cg.shared.global [%0], [%1], 16;" :: "r"(saddr), "l"(gaddr));
}
__device__ __forceinline__ void cp_commit() {
    asm volatile("cp.async.commit_group;" ::: "memory");
}
template<int N>
__device__ __forceinline__ void cp_wait() {
    asm volatile("cp.async.wait_group %0;" :: "n"(N) : "memory");
}
__device__ __forceinline__ void ldsm_x4(uint32_t* r, uint32_t addr) {
    asm volatile("ldmatrix.sync.aligned.m8n8.x4.shared.b16 {%0,%1,%2,%3}, [%4];"
        : "=r"(r[0]), "=r"(r[1]), "=r"(r[2]), "=r"(r[3]) : "r"(addr));
}
__device__ __forceinline__ void mma_bf16(float* c, const uint32_t* a, const uint32_t* b) {
    asm volatile(
        "mma.sync.aligned.m16n8k16.row.col.f32.bf16.bf16.f32 "
        "{%0,%1,%2,%3}, {%4,%5,%6,%7}, {%8,%9}, {%0,%1,%2,%3};"
        : "+f"(c[0]), "+f"(c[1]), "+f"(c[2]), "+f"(c[3])
        : "r"(a[0]), "r"(a[1]), "r"(a[2]), "r"(a[3]), "r"(b[0]), "r"(b[1]));
}

// ---------------------------------------------------------------------------
// Split fp32 -> bf16 hi/lo
// ---------------------------------------------------------------------------
__global__ void __launch_bounds__(256) split2_kernel(
    const float* __restrict__ src, __nv_bfloat16* __restrict__ hi,
    __nv_bfloat16* __restrict__ lo, int n4)
{
    int i = blockIdx.x * 256 + threadIdx.x;
    if (i >= n4) return;
    float4 v = ((const float4*)src)[i];
    ushort4 hv, lv;
    float* vp = &v.x;
    unsigned short* hp = &hv.x;
    unsigned short* lp = &lv.x;
    #pragma unroll
    for (int j = 0; j < 4; ++j) {
        __nv_bfloat16 h = __float2bfloat16(vp[j]);
        __nv_bfloat16 l = __float2bfloat16(vp[j] - __bfloat162float(h));
        hp[j] = __bfloat16_as_ushort(h);
        lp[j] = __bfloat16_as_ushort(l);
    }
    ((ushort4*)hi)[i] = hv;
    ((ushort4*)lo)[i] = lv;
}

// Transpose + split: w [K][N] fp32 -> wT hi/lo [N][K] bf16
__global__ void __launch_bounds__(256) tsplit_kernel(
    const float* __restrict__ w, __nv_bfloat16* __restrict__ hi,
    __nv_bfloat16* __restrict__ lo, int K, int N)
{
    int idx = blockIdx.x * 256 + threadIdx.x;
    if (idx >= K * N) return;
    int k = idx / N, n = idx - k * N;
    float v = w[idx];
    __nv_bfloat16 h = __float2bfloat16(v);
    __nv_bfloat16 l = __float2bfloat16(v - __bfloat162float(h));
    hi[(size_t)n * K + k] = h;
    lo[(size_t)n * K + k] = l;
}

// ---------------------------------------------------------------------------
// mma.sync split-bf16 GEMM: C[M,ldc] = A[M,K] @ B^T (B stored [N][K] K-major)
// BM=BN=128, BK=32, 256 threads (8 warps 4x2, 32x64 warp tiles),
// 3-stage cp.async pipeline, padding-free XOR-swizzled smem (2 CTAs/SM),
// SINGLE __syncthreads per k-chunk (loads for kt+2 target the buffer all
// warps finished reading at kt-1; the top-of-loop barrier orders that).
// Swizzle: 64B rows of 4x16B chunks; phys_chunk = chunk ^ ((row>>1)&3).
// ACT: elu(x)+1 on output cols < 2048.
// ---------------------------------------------------------------------------
#define TILE_B (128*64)            // 8192 B per operand tile
#define STAGE_B (4*TILE_B)         // Ahi|Alo|Bhi|Blo = 32768 B
#define NSTAGE 3
#define HS_TOTAL (NSTAGE*STAGE_B)  // 98304 B

template<bool ACT>
__global__ void __launch_bounds__(256, 2)
hmma_kernel(const __nv_bfloat16* __restrict__ Ahi, const __nv_bfloat16* __restrict__ Alo,
            const __nv_bfloat16* __restrict__ Bhi, const __nv_bfloat16* __restrict__ Blo,
            float* __restrict__ C, int ldc, int K)
{
    extern __shared__ __align__(128) char smem[];
    const uint32_t sbase = smem_u32(smem);
    const int tid = threadIdx.x;
    const int wid = tid >> 5, l = tid & 31;
    const int n0 = blockIdx.x * 128;
    const int m0 = blockIdx.y * 128;
    const int wm = (wid & 3) * 32;     // warp m offset
    const int wn = (wid >> 2) * 64;    // warp n offset

    // ---- loader mapping: thread -> (row, 32B chunk-pair), swizzled dest ----
    const int lrow = tid >> 1;          // 0..127
    const int c0   = (tid & 1) * 2;     // logical chunk 0 or 2
    const int lsw  = (lrow >> 1) & 3;   // swizzle key
    const char* gA[4];
    gA[0] = (const char*)(Ahi + (size_t)(m0 + lrow) * K);
    gA[1] = (const char*)(Alo + (size_t)(m0 + lrow) * K);
    gA[2] = (const char*)(Bhi + (size_t)(n0 + lrow) * K);
    gA[3] = (const char*)(Blo + (size_t)(n0 + lrow) * K);
    const uint32_t sd0 = sbase + lrow * 64 + (uint32_t)((c0 ^ lsw) << 4);
    const uint32_t sd1 = sbase + lrow * 64 + (uint32_t)(((c0 + 1) ^ lsw) << 4);

    const int nkt = K >> 5;             // 32-element k chunks

    auto load_stage = [&](int kt, int buf) {
        const uint32_t b0 = sd0 + buf * STAGE_B;
        const uint32_t b1 = sd1 + buf * STAGE_B;
        const int goff = kt * 64;       // bytes along K
        #pragma unroll
        for (int t = 0; t < 4; ++t) {
            cp_async16(b0 + t * TILE_B, gA[t] + goff + c0 * 16);
            cp_async16(b1 + t * TILE_B, gA[t] + goff + c0 * 16 + 16);
        }
    };

    load_stage(0, 0); cp_commit();
    load_stage(1, 1); cp_commit();

    float acc[16][4];
    #pragma unroll
    for (int i = 0; i < 16; ++i)
        #pragma unroll
        for (int j = 0; j < 4; ++j) acc[i][j] = 0.0f;

    // ---- ldmatrix fragment offsets, fully precomputed (incl. swizzle) ----
    // aoff[kk][mt], boff[kk][ng]: byte offsets within a stage
    uint32_t aoff[2][2], boff[2][4];
    {
        const uint32_t caA = (uint32_t)(l >> 4);
        const uint32_t caB = (uint32_t)((l >> 3) & 1);
        #pragma unroll
        for (int mt = 0; mt < 2; ++mt) {
            const int r = wm + (l & 15) + mt * 16;
            const uint32_t sw = (uint32_t)((r >> 1) & 3);
            #pragma unroll
            for (int kk = 0; kk < 2; ++kk)
                aoff[kk][mt] = (uint32_t)(r * 64) + (((kk * 2 + caA) ^ sw) << 4);
        }
        #pragma unroll
        for (int ng = 0; ng < 4; ++ng) {
            const int r = wn + ((l >> 4) & 1) * 8 + (l & 7) + ng * 16;
            const uint32_t sw = (uint32_t)((r >> 1) & 3);
            #pragma unroll
            for (int kk = 0; kk < 2; ++kk)
                boff[kk][ng] = (uint32_t)(r * 64) + (((kk * 2 + caB) ^ sw) << 4);
        }
    }

    int buf = 0, lbuf = 2;
    #pragma unroll 1
    for (int kt = 0; kt < nkt; ++kt) {
        cp_wait<NSTAGE - 2>();
        __syncthreads();
        // issue next stage's loads immediately (buffer lbuf = (kt+2)%3, which
        // all warps finished reading at iteration kt-1; barrier above orders it)
        if (kt + NSTAGE - 1 < nkt) load_stage(kt + NSTAGE - 1, lbuf);
        cp_commit();

        const uint32_t sb = sbase + buf * STAGE_B;
        #pragma unroll
        for (int kk = 0; kk < 2; ++kk) {
            uint32_t ah[2][4], al[2][4], bh[4][4], bl[4][4];
            #pragma unroll
            for (int mt = 0; mt < 2; ++mt) {
                ldsm_x4(ah[mt], sb + 0*TILE_B + aoff[kk][mt]);
                ldsm_x4(al[mt], sb + 1*TILE_B + aoff[kk][mt]);
            }
            #pragma unroll
            for (int ng = 0; ng < 4; ++ng) {
                ldsm_x4(bh[ng], sb + 2*TILE_B + boff[kk][ng]);
                ldsm_x4(bl[ng], sb + 3*TILE_B + boff[kk][ng]);
            }
            #pragma unroll
            for (int mt = 0; mt < 2; ++mt)
                #pragma unroll
                for (int nt = 0; nt < 8; ++nt) {
                    float* c = acc[mt * 8 + nt];
                    const uint32_t* bhp = &bh[nt >> 1][(nt & 1) * 2];
                    const uint32_t* blp = &bl[nt >> 1][(nt & 1) * 2];
                    mma_bf16(c, ah[mt], bhp);
                    mma_bf16(c, ah[mt], blp);
                    mma_bf16(c, al[mt], bhp);
                }
        }
        buf  = (buf  == NSTAGE - 1) ? 0 : buf + 1;
        lbuf = (lbuf == NSTAGE - 1) ? 0 : lbuf + 1;
    }

    // epilogue: direct float2 stores (+ optional elu+1)
    const bool doact = ACT && (n0 < 2048);
    const int erow = m0 + wm + (l >> 2);
    const int ecol = n0 + wn + (l & 3) * 2;
    #pragma unroll
    for (int mt = 0; mt < 2; ++mt)
        #pragma unroll
        for (int nt = 0; nt < 8; ++nt) {
            float v0 = acc[mt*8+nt][0], v1 = acc[mt*8+nt][1];
            float v2 = acc[mt*8+nt][2], v3 = acc[mt*8+nt][3];
            if (doact) {
                v0 = (v0 > 0.f) ? v0 + 1.f : expf(v0);
                v1 = (v1 > 0.f) ? v1 + 1.f : expf(v1);
                v2 = (v2 > 0.f) ? v2 + 1.f : expf(v2);
                v3 = (v3 > 0.f) ? v3 + 1.f : expf(v3);
            }
            float2 o0; o0.x = v0; o0.y = v1;
            float2 o1; o1.x = v2; o1.y = v3;
            const int r = erow + mt * 16;
            const int cc = ecol + nt * 8;
            *(float2*)(C + (size_t)r * ldc + cc) = o0;
            *(float2*)(C + (size_t)(r + 8) * ldc + cc) = o1;
        }
}

// ---------------------------------------------------------------------------
// Zero kv/ksum accumulators
// ---------------------------------------------------------------------------
__global__ void zero_kv_kernel() {
    int i = blockIdx.x * 256 + threadIdx.x;
    if (i < BATCH*NH*DK*DK) g_kv[i] = 0.0f;
    if (i < BATCH*NH*DK)    g_ksum[i] = 0.0f;
}

// ---------------------------------------------------------------------------
// kv[b,h,d,f] = sum_n k[b,n,h,d] * v[b,n,h,f];  ksum[b,h,d] = sum_n k
// ---------------------------------------------------------------------------
__global__ void __launch_bounds__(256) kv_kernel() {
    const int bh = blockIdx.x;
    const int b  = bh >> 4, h = bh & 15;
    const int n0 = blockIdx.y * 512;

    __shared__ float ks[8][64];
    __shared__ float vs[8][64];

    const int tid = threadIdx.x;
    const int d   = tid & 63;
    const int fg  = tid >> 6;
    const int rr   = tid >> 5;
    const int half = (tid >> 4) & 1;
    const int c4   = tid & 15;

    float4 acc[4];
    #pragma unroll
    for (int i = 0; i < 4; ++i) acc[i] = make_float4(0.f,0.f,0.f,0.f);
    float ksacc = 0.0f;

    for (int r0 = 0; r0 < 512; r0 += 8) {
        const size_t rowbase = (size_t)(b*SEQ + n0 + r0 + rr) * QKVN;
        const float4 val = *(const float4*)(g_qkv + rowbase
                            + (half ? 2048 : 1024) + h*64 + c4*4);
        __syncthreads();
        if (half == 0) *(float4*)&ks[rr][c4*4] = val;
        else           *(float4*)&vs[rr][c4*4] = val;
        __syncthreads();
        #pragma unroll
        for (int r = 0; r < 8; ++r) {
            const float kd = ks[r][d];
            ksacc += kd;
            #pragma unroll
            for (int i4 = 0; i4 < 4; ++i4) {
                const float4 vv = *(const float4*)&vs[r][fg*16 + i4*4];
                acc[i4].x += kd * vv.x; acc[i4].y += kd * vv.y;
                acc[i4].z += kd * vv.z; acc[i4].w += kd * vv.w;
            }
        }
    }

    float* dst = g_kv + ((size_t)bh * DK + d) * DK + fg*16;
    #pragma unroll
    for (int i4 = 0; i4 < 4; ++i4) {
        atomicAdd(dst + i4*4 + 0, acc[i4].x);
        atomicAdd(dst + i4*4 + 1, acc[i4].y);
        atomicAdd(dst + i4*4 + 2, acc[i4].z);
        atomicAdd(dst + i4*4 + 3, acc[i4].w);
    }
    if (fg == 0) atomicAdd(&g_ksum[bh*DK + d], ksacc);
}

// ---------------------------------------------------------------------------
// attn = (q @ kv) / (q . ksum + 1e-6), output split to bf16 hi/lo
// ---------------------------------------------------------------------------
__global__ void __launch_bounds__(256) attn_kernel() {
    const int bh = blockIdx.y;
    const int b  = bh >> 4, hh = bh & 15;
    const int n0 = blockIdx.x * 64;

    __shared__ float kvs[64][64];
    __shared__ float qs[64][64];
    __shared__ float ksums[64];
    __shared__ float dens[64];

    const int tid = threadIdx.x;

    {
        const float4* src = (const float4*)(g_kv + (size_t)bh * DK * DK);
        float4* dst = (float4*)kvs;
        for (int i = tid; i < 1024; i += 256) dst[i] = src[i];
    }
    for (int j = tid; j < 1024; j += 256) {
        const int r = j >> 4, c = j & 15;
        ((float4*)qs)[j] = *(const float4*)(g_qkv
            + (size_t)(b*SEQ + n0 + r) * QKVN + hh*64 + c*4);
    }
    if (tid < 16)
        ((float4*)ksums)[tid] = *(const float4*)(g_ksum + bh*DK + tid*4);
    __syncthreads();

    if (tid < 64) {
        float s = 0.0f;
        #pragma unroll
        for (int dd = 0; dd < 64; ++dd) s += qs[tid][dd] * ksums[dd];
        dens[tid] = s + 1e-6f;
    }
    __syncthreads();

    const int rg = tid >> 4;
    const int f4 = tid & 15;
    float4 acc[4];
    #pragma unroll
    for (int r = 0; r < 4; ++r) acc[r] = make_float4(0.f,0.f,0.f,0.f);

    #pragma unroll 8
    for (int dd = 0; dd < 64; ++dd) {
        const float4 kvv = *(const float4*)&kvs[dd][f4*4];
        #pragma unroll
        for (int r = 0; r < 4; ++r) {
            const float qv = qs[rg*4 + r][dd];
            acc[r].x += qv * kvv.x; acc[r].y += qv * kvv.y;
            acc[r].z += qv * kvv.z; acc[r].w += qv * kvv.w;
        }
    }

    #pragma unroll
    for (int r = 0; r < 4; ++r) {
        const int row = n0 + rg*4 + r;
        const float inv = 1.0f / dens[rg*4 + r];
        float o[4];
        o[0] = acc[r].x * inv; o[1] = acc[r].y * inv;
        o[2] = acc[r].z * inv; o[3] = acc[r].w * inv;
        ushort4 hv, lv;
        unsigned short* hp = &hv.x;
        unsigned short* lp = &lv.x;
        #pragma unroll
        for (int j = 0; j < 4; ++j) {
            __nv_bfloat16 hbf = __float2bfloat16(o[j]);
            __nv_bfloat16 lbf = __float2bfloat16(o[j] - __bfloat162float(hbf));
            hp[j] = __bfloat16_as_ushort(hbf);
            lp[j] = __bfloat16_as_ushort(lbf);
        }
        const size_t idx = ((size_t)(b*SEQ + row) * DMODEL + hh*64 + f4*4) >> 2;
        ((ushort4*)g_ahi)[idx] = hv;
        ((ushort4*)g_alo)[idx] = lv;
    }
}

// ---------------------------------------------------------------------------
extern "C" void kernel_launch(void* const* d_in, const int* in_sizes, int n_in,
                              void* d_out, int out_size)
{
    const float* x    = (const float*)d_in[0];
    const float* wqkv = (const float*)d_in[1];
    const float* wo   = (const float*)d_in[2];
    float* out = (float*)d_out;

    float *qkv_p = nullptr;
    __nv_bfloat16 *xhi, *xlo, *ahi, *alo, *wqh, *wql, *woh, *wol;
    cudaGetSymbolAddress((void**)&qkv_p, g_qkv);
    cudaGetSymbolAddress((void**)&xhi, g_xhi);
    cudaGetSymbolAddress((void**)&xlo, g_xlo);
    cudaGetSymbolAddress((void**)&ahi, g_ahi);
    cudaGetSymbolAddress((void**)&alo, g_alo);
    cudaGetSymbolAddress((void**)&wqh, g_wqh);
    cudaGetSymbolAddress((void**)&wql, g_wql);
    cudaGetSymbolAddress((void**)&woh, g_woh);
    cudaGetSymbolAddress((void**)&wol, g_wol);

    cudaFuncSetAttribute(hmma_kernel<true>,
        cudaFuncAttributeMaxDynamicSharedMemorySize, HS_TOTAL);
    cudaFuncSetAttribute(hmma_kernel<false>,
        cudaFuncAttributeMaxDynamicSharedMemorySize, HS_TOTAL);

    // 1) split inputs
    {
        int n4 = MTOT * DMODEL / 4;
        split2_kernel<<<(n4 + 255)/256, 256>>>(x, xhi, xlo, n4);
    }
    tsplit_kernel<<<(DMODEL*QKVN + 255)/256, 256>>>(wqkv, wqh, wql, DMODEL, QKVN);
    tsplit_kernel<<<(DMODEL*DMODEL + 255)/256, 256>>>(wo, woh, wol, DMODEL, DMODEL);

    // 2) QKV projection (mma.sync bf16 split) + fused elu+1 on q,k columns
    hmma_kernel<true><<<dim3(QKVN/128, MTOT/128), 256, HS_TOTAL>>>(
        xhi, xlo, wqh, wql, qkv_p, QKVN, DMODEL);

    // 3) zero accumulators
    zero_kv_kernel<<<(BATCH*NH*DK*DK + 255)/256, 256>>>();

    // 4) kv / ksum reductions
    kv_kernel<<<dim3(BATCH*NH, 16), 256>>>();

    // 5) attn (outputs bf16 hi/lo)
    attn_kernel<<<dim3(SEQ/64, BATCH*NH), 256>>>();

    // 6) output projection (mma.sync bf16 split)
    hmma_kernel<false><<<dim3(DMODEL/128, MTOT/128), 256, HS_TOTAL>>>(
        ahi, alo, woh, wol, out, DMODEL, DMODEL);
}